// round 13
// baseline (speedup 1.0000x reference)
#include <cuda_runtime.h>
#include <cuda_fp16.h>
#include <cstdint>

#define NN   2000
#define HH   4
#define NDm  64
#define KK   20
#define TILE 8
#define BLT  128          // B*L = 4*32
#define DD   64
#define OUT_ELEMS (4*2000*32*64)
#define CCAP 512
#define MARKV (-3.0e38f)
#define XS_STRIDE 68

// ---------------- scratch (device globals; no allocation) ----------------
__device__ __align__(16) __half g_supph[(size_t)BLT*NN*DD];   // 32.8 MB fp16 support
__device__ int   g_tki[HH*NN*KK];
__device__ float g_tkv[HH*NN*KK];
__device__ int   g_colcnt[NN];
__device__ int   g_ci[(size_t)NN*CCAP];
__device__ float g_cv[(size_t)NN*CCAP];
__device__ float g_fa_fb[(size_t)NN*NN];         // fallback final_adj (16 MB)

// ---------------- 0: zero counters + final_adj region ----------------
__global__ void zero_kernel(float* fa) {
    int idx = blockIdx.x * blockDim.x + threadIdx.x;
    if (idx < NN) g_colcnt[idx] = 0;
    size_t stride = (size_t)gridDim.x * blockDim.x;
    for (size_t p = idx; p < (size_t)NN * NN; p += stride) fa[p] = 0.f;
}

// ---------------- 1: FUSED scores+topk / support kernel ----------------
// grid = 3000 blocks of 256 threads, 66048 B dyn smem.
//   bx % 3 == 0  -> scores/topk block, id = bx/3           (1000 blocks)
//   else         -> support block,    id = bx - bx/3 - 1   (2000 blocks)
__global__ __launch_bounds__(256) void fused_scores_support_kernel(
    const float* __restrict__ e1, const float* __restrict__ e2,
    const float* __restrict__ temp,
    const float* __restrict__ x, const float* __restrict__ W)
{
    extern __shared__ float sm[];
    int bx = blockIdx.x;
    int tid = threadIdx.x;

    if (bx % 3 == 0) {
        // ================= scores + top-20 =================
        int sidb = bx / 3;
        float* s   = sm;                // [TILE][NN] raw scores
        float* e1s = sm + TILE * NN;    // [TILE][NDm]

        int h  = sidb / (NN / TILE);
        int n0 = (sidb % (NN / TILE)) * TILE;

        for (int i = tid; i < TILE * NDm; i += blockDim.x)
            e1s[i] = e1[((size_t)h * NN + n0 + i / NDm) * NDm + (i % NDm)];
        __syncthreads();

        // register-blocked GEMM: each thread -> all 8 rows x 4 consecutive m.
        const float* e2h = e2 + (size_t)h * NDm * NN;
        for (int m0 = tid * 4; m0 < NN; m0 += 1024) {
            float acc[TILE][4];
#pragma unroll
            for (int r = 0; r < TILE; r++)
#pragma unroll
                for (int mm = 0; mm < 4; mm++) acc[r][mm] = 0.f;

#pragma unroll 4
            for (int d4 = 0; d4 < NDm; d4 += 4) {
                float4 e1v[TILE];
#pragma unroll
                for (int r = 0; r < TILE; r++)
                    e1v[r] = *(const float4*)&e1s[r * NDm + d4];
                float4 b0 = *(const float4*)(e2h + (size_t)(d4 + 0) * NN + m0);
                float4 b1 = *(const float4*)(e2h + (size_t)(d4 + 1) * NN + m0);
                float4 b2 = *(const float4*)(e2h + (size_t)(d4 + 2) * NN + m0);
                float4 b3 = *(const float4*)(e2h + (size_t)(d4 + 3) * NN + m0);
#pragma unroll
                for (int r = 0; r < TILE; r++) {
                    acc[r][0] = fmaf(e1v[r].x, b0.x, acc[r][0]);
                    acc[r][1] = fmaf(e1v[r].x, b0.y, acc[r][1]);
                    acc[r][2] = fmaf(e1v[r].x, b0.z, acc[r][2]);
                    acc[r][3] = fmaf(e1v[r].x, b0.w, acc[r][3]);
                    acc[r][0] = fmaf(e1v[r].y, b1.x, acc[r][0]);
                    acc[r][1] = fmaf(e1v[r].y, b1.y, acc[r][1]);
                    acc[r][2] = fmaf(e1v[r].y, b1.z, acc[r][2]);
                    acc[r][3] = fmaf(e1v[r].y, b1.w, acc[r][3]);
                    acc[r][0] = fmaf(e1v[r].z, b2.x, acc[r][0]);
                    acc[r][1] = fmaf(e1v[r].z, b2.y, acc[r][1]);
                    acc[r][2] = fmaf(e1v[r].z, b2.z, acc[r][2]);
                    acc[r][3] = fmaf(e1v[r].z, b2.w, acc[r][3]);
                    acc[r][0] = fmaf(e1v[r].w, b3.x, acc[r][0]);
                    acc[r][1] = fmaf(e1v[r].w, b3.y, acc[r][1]);
                    acc[r][2] = fmaf(e1v[r].w, b3.z, acc[r][2]);
                    acc[r][3] = fmaf(e1v[r].w, b3.w, acc[r][3]);
                }
            }
#pragma unroll
            for (int r = 0; r < TILE; r++)
                *(float4*)&s[r * NN + m0] = *(float4*)acc[r];
        }
        __syncthreads();

        int w = tid >> 5, lane = tid & 31;
        float invT = 1.0f / temp[h];
        float* sw = s + w * NN;

        float v0 = -1.f, v1 = -1.f, v2 = -1.f, v3 = -1.f;
        int   m0i = 0,   m1i = 0,   m2i = 0,   m3i = 0;
#define INSERT_CAND(a, m) do { \
            if ((a) > v3) { \
                if ((a) > v0)      { v3=v2;m3i=m2i; v2=v1;m2i=m1i; v1=v0;m1i=m0i; v0=(a);m0i=(m); } \
                else if ((a) > v1) { v3=v2;m3i=m2i; v2=v1;m2i=m1i; v1=(a);m1i=(m); } \
                else if ((a) > v2) { v3=v2;m3i=m2i; v2=(a);m2i=(m); } \
                else               { v3=(a);m3i=(m); } \
            } } while (0)

        for (int m = lane; m < NN; m += 32) {
            float raw = sw[m];
            float a = (raw < -1e30f) ? -1.f : fmaxf(raw, 0.f) * invT;
            INSERT_CAND(a, m);
        }

        int base = (h * NN + n0 + w) * KK;
        float M = 0.f, ssel = 0.f;
        for (int k = 0; k < KK; k++) {
            float best = v0; int bm = m0i;
#pragma unroll
            for (int o = 16; o; o >>= 1) {
                float ov = __shfl_xor_sync(0xffffffffu, best, o);
                int   oi = __shfl_xor_sync(0xffffffffu, bm,   o);
                if (ov > best || (ov == best && oi < bm)) { best = ov; bm = oi; }
            }
            if (k == 0) M = best;
            float e = __expf(best - M);
            ssel += e;
            if (lane == 0) { g_tki[base + k] = bm; g_tkv[base + k] = e; }
            if (lane == (bm & 31)) {
                sw[bm] = MARKV;
                v0 = v1; m0i = m1i; v1 = v2; m1i = m2i; v2 = v3; m2i = m3i; v3 = -1.f;
                if (v0 < 0.f && k < KK - 1) {
                    v0 = v1 = v2 = v3 = -1.f;
                    for (int m = lane; m < NN; m += 32) {
                        float raw = sw[m];
                        float a = (raw < -1e30f) ? -1.f : fmaxf(raw, 0.f) * invT;
                        INSERT_CAND(a, m);
                    }
                }
            }
        }
#undef INSERT_CAND
        if (lane < KK) g_tkv[base + lane] = g_tkv[base + lane] / ssel;

    } else {
        // ================= support = fp16( xr @ W ), 128 rows/block =================
        int sid = bx - bx / 3 - 1;       // 0..1999
        int row0 = sid * 128;
        float* xs = sm;                  // [128][XS_STRIDE]
        float* wt = sm + 128 * XS_STRIDE; // [64][XS_STRIDE]

        for (int k = tid; k < 1024; k += 256) {
            int d = k >> 4, o4 = (k & 15) * 4;
            float4 w = ((const float4*)W)[k];
            wt[(o4 + 0) * XS_STRIDE + d] = w.x;
            wt[(o4 + 1) * XS_STRIDE + d] = w.y;
            wt[(o4 + 2) * XS_STRIDE + d] = w.z;
            wt[(o4 + 3) * XS_STRIDE + d] = w.w;
        }
        for (int k = tid; k < 2048; k += 256) {
            int rr = k >> 4, f4 = k & 15;
            int r = row0 + rr;
            int bl = r / NN, n = r - bl * NN;
            int b = bl >> 5, l = bl & 31;
            float4 v = ((const float4*)(x + (((size_t)(b * NN + n) * 32) + l) * 64))[f4];
            *(float4*)&xs[rr * XS_STRIDE + f4 * 4] = v;
        }
        __syncthreads();

        int tr = tid & 15, to = tid >> 4;   // 16 row-groups x 16 col-groups
        float acc[8][4];
#pragma unroll
        for (int i = 0; i < 8; i++)
#pragma unroll
            for (int j = 0; j < 4; j++) acc[i][j] = 0.f;

#pragma unroll 4
        for (int d4 = 0; d4 < 64; d4 += 4) {
            float4 xv[8], wv[4];
#pragma unroll
            for (int i = 0; i < 8; i++) xv[i] = *(const float4*)&xs[(tr + 16 * i) * XS_STRIDE + d4];
#pragma unroll
            for (int j = 0; j < 4; j++) wv[j] = *(const float4*)&wt[(to * 4 + j) * XS_STRIDE + d4];
#pragma unroll
            for (int i = 0; i < 8; i++)
#pragma unroll
                for (int j = 0; j < 4; j++) {
                    acc[i][j] = fmaf(xv[i].x, wv[j].x, acc[i][j]);
                    acc[i][j] = fmaf(xv[i].y, wv[j].y, acc[i][j]);
                    acc[i][j] = fmaf(xv[i].z, wv[j].z, acc[i][j]);
                    acc[i][j] = fmaf(xv[i].w, wv[j].w, acc[i][j]);
                }
        }

#pragma unroll
        for (int i = 0; i < 8; i++) {
            int r = row0 + tr + 16 * i;
            __half2 h0 = __floats2half2_rn(acc[i][0], acc[i][1]);
            __half2 h1 = __floats2half2_rn(acc[i][2], acc[i][3]);
            uint2 pk;
            pk.x = *(uint32_t*)&h0;
            pk.y = *(uint32_t*)&h1;
            *(uint2*)(g_supph + (size_t)r * 64 + to * 4) = pk;
        }
    }
}

// ---------------- 2: per-row union + edge MLP -> column lists + dense fa ----------------
// one warp per row i; grid = N/8 blocks of 256 threads
__global__ __launch_bounds__(256) void build_rows_kernel(
    const float* __restrict__ ew1, const float* __restrict__ eb1,
    const float* __restrict__ ew2, const float* __restrict__ eb2,
    float* __restrict__ fa)
{
    __shared__ float s_ew1[HH * 8];
    __shared__ float s_eb1[8];
    __shared__ float s_ew2[8];
    __shared__ int   s_js[8][80];
    __shared__ float s_vs[8][80];

    int tid = threadIdx.x;
    if (tid < 32) s_ew1[tid] = ew1[tid];
    else if (tid < 40) s_eb1[tid - 32] = eb1[tid - 32];
    else if (tid < 48) s_ew2[tid - 40] = ew2[tid - 40];
    float beta2 = eb2[0];
    __syncthreads();

    int w = tid >> 5, lane = tid & 31;
    int i = blockIdx.x * 8 + w;

    for (int e = lane; e < 80; e += 32) {
        int hh = e / KK, k = e % KK;
        s_js[w][e] = g_tki[(hh * NN + i) * KK + k];
        s_vs[w][e] = g_tkv[(hh * NN + i) * KK + k];
    }
    __syncwarp();

    for (int p = 0; p < 3; p++) {
        int e = lane + p * 32;
        bool owned = false;
        int j = -1;
        if (e < 80) {
            j = s_js[w][e];
            owned = true;
            for (int q = 0; q < e; q++)
                if (s_js[w][q] == j) { owned = false; break; }
        }
        if (owned) {
            float v[HH];
            float vsum = 0.f;
#pragma unroll
            for (int hh = 0; hh < HH; hh++) {
                float vv = 0.f;
                for (int k = 0; k < KK; k++)
                    if (s_js[w][hh * KK + k] == j) { vv = s_vs[w][hh * KK + k]; break; }
                v[hh] = vv; vsum += vv;
            }
            float ewv = beta2;
#pragma unroll
            for (int c = 0; c < 8; c++) {
                float hid = s_eb1[c];
#pragma unroll
                for (int hh = 0; hh < HH; hh++) hid = fmaf(v[hh], s_ew1[hh * 8 + c], hid);
                hid = fmaxf(hid, 0.f);
                ewv = fmaf(hid, s_ew2[c], ewv);
            }
            float sig  = 1.f / (1.f + __expf(-ewv));
            float favv = sig * (vsum * 0.25f);
            int pos = atomicAdd(&g_colcnt[j], 1);
            if (pos < CCAP) {
                g_ci[(size_t)j * CCAP + pos] = i;
                g_cv[(size_t)j * CCAP + pos] = favv;
            }
            fa[(size_t)i * NN + j] = favv;
        }
    }
}

// ---------------- 3: sparse out[b,c,l,:] = sum_e w_e * support[bl, j_e, :] + bias ----------------
// one block per column c; 256 threads = 8 d-octets x 32 bl-groups; 4 bl iters
__global__ __launch_bounds__(256) void spmm_kernel(
    const float* __restrict__ bias, float* __restrict__ out)
{
    __shared__ int   sj[CCAP];
    __shared__ float sv[CCAP];
    int c = blockIdx.x;
    int tid = threadIdx.x;
    int q = tid & 7;        // d octet: d = 8q .. 8q+7
    int g = tid >> 3;       // 0..31
    int cnt = g_colcnt[c];
    if (cnt > CCAP) cnt = CCAP;
    size_t start = (size_t)c * CCAP;

    float acc[4][8];
#pragma unroll
    for (int it = 0; it < 4; it++)
#pragma unroll
        for (int j = 0; j < 8; j++) acc[it][j] = 0.f;

    const uint4* supp4 = (const uint4*)g_supph;   // 8 halves per uint4

    for (int e = tid; e < cnt; e += 256) {
        sj[e] = g_ci[start + e];
        sv[e] = g_cv[start + e];
    }
    __syncthreads();
    for (int e = 0; e < cnt; e++) {
        float wv = sv[e];
        int   i  = sj[e];
#pragma unroll
        for (int it = 0; it < 4; it++) {
            int bl = it * 32 + g;
            uint4 h4 = supp4[(size_t)(bl * NN + i) * 8 + q];
            const __half2* hh = (const __half2*)&h4;
#pragma unroll
            for (int j = 0; j < 4; j++) {
                float2 f = __half22float2(hh[j]);
                acc[it][2 * j]     = fmaf(wv, f.x, acc[it][2 * j]);
                acc[it][2 * j + 1] = fmaf(wv, f.y, acc[it][2 * j + 1]);
            }
        }
    }

    float bv[8];
#pragma unroll
    for (int j = 0; j < 8; j++) bv[j] = bias[q * 8 + j];

#pragma unroll
    for (int it = 0; it < 4; it++) {
        int bl = it * 32 + g;
        int b = bl >> 5, l = bl & 31;
        float4 r0, r1;
        r0.x = acc[it][0] + bv[0]; r0.y = acc[it][1] + bv[1];
        r0.z = acc[it][2] + bv[2]; r0.w = acc[it][3] + bv[3];
        r1.x = acc[it][4] + bv[4]; r1.y = acc[it][5] + bv[5];
        r1.z = acc[it][6] + bv[6]; r1.w = acc[it][7] + bv[7];
        size_t ob = (size_t)((b * NN + c) * 32 + l) * 16 + q * 2;
        ((float4*)out)[ob]     = r0;
        ((float4*)out)[ob + 1] = r1;
    }
}

// ---------------- launch ----------------
extern "C" void kernel_launch(void* const* d_in, const int* in_sizes, int n_in,
                              void* d_out, int out_size)
{
    const float* x      = (const float*)d_in[0];
    const float* e1     = (const float*)d_in[1];
    const float* e2     = (const float*)d_in[2];
    const float* temp   = (const float*)d_in[3];
    const float* ew1    = (const float*)d_in[4];
    const float* eb1    = (const float*)d_in[5];
    const float* ew2    = (const float*)d_in[6];
    const float* eb2    = (const float*)d_in[7];
    const float* weight = (const float*)d_in[8];
    const float* bias   = (const float*)d_in[9];
    float* out = (float*)d_out;

    // final_adj destination: appended after out if there is room, else fallback scratch
    float* fa;
    if (out_size >= OUT_ELEMS + NN * NN) {
        fa = out + OUT_ELEMS;
    } else {
        void* p = nullptr;
        cudaGetSymbolAddress(&p, g_fa_fb);
        fa = (float*)p;
    }

    const int smem_fused = (TILE * NN + TILE * NDm) * sizeof(float);  // 66048 B
    cudaFuncSetAttribute(fused_scores_support_kernel,
                         cudaFuncAttributeMaxDynamicSharedMemorySize, smem_fused);

    zero_kernel<<<2048, 256>>>(fa);
    fused_scores_support_kernel<<<3000, 256, smem_fused>>>(e1, e2, temp, x, weight);
    build_rows_kernel<<<NN / 8, 256>>>(ew1, eb1, ew2, eb2, fa);
    spmm_kernel<<<NN, 256>>>(bias, out);
}

// round 14
// speedup vs baseline: 1.2469x; 1.2469x over previous
#include <cuda_runtime.h>
#include <cuda_fp16.h>
#include <cstdint>

#define NN   2000
#define HH   4
#define NDm  64
#define KK   20
#define TILE 8
#define BLT  128          // B*L = 4*32
#define DD   64
#define OUT_ELEMS (4*2000*32*64)
#define NNZ_CAP   (NN*80)
#define MARKV (-3.0e38f)
#define XS_STRIDE 68

// ---------------- scratch (device globals; no allocation) ----------------
__device__ __align__(16) __half g_supph[(size_t)BLT*NN*DD];   // 32.8 MB fp16 support
__device__ int   g_tki[HH*NN*KK];
__device__ float g_tkv[HH*NN*KK];
__device__ int   g_rowj[NN*80];
__device__ float g_rowv[NN*80];
__device__ int   g_rowcnt[NN];
__device__ int   g_colcnt[NN];
__device__ int   g_colptr[NN];
__device__ int   g_colcur[NN];
__device__ int   g_ci[NNZ_CAP];
__device__ float g_cv[NNZ_CAP];
__device__ float g_fa_fb[(size_t)NN*NN];         // fallback final_adj (16 MB)

// ---------------- 1: FUSED scores+topk / support kernel (+ fa/colcnt zeroing) ----------------
// grid = 3000 blocks of 256 threads, 66048 B dyn smem.
//   bx % 3 == 0  -> scores/topk block, id = bx/3           (1000 blocks)
//   else         -> support block,    id = bx - bx/3 - 1   (2000 blocks)
// Prologue: every block zeroes a disjoint slice of fa (consumed only by
// build_rows, which launches after this kernel); blocks 0..7 zero g_colcnt.
__global__ __launch_bounds__(256) void fused_scores_support_kernel(
    const float* __restrict__ e1, const float* __restrict__ e2,
    const float* __restrict__ temp,
    const float* __restrict__ x, const float* __restrict__ W,
    float* __restrict__ fa)
{
    extern __shared__ float sm[];
    int bx = blockIdx.x;
    int tid = threadIdx.x;

    // ---- zero prologue (disjoint slices; no races) ----
    {
        if (bx < 8) {
            int c = bx * 256 + tid;
            if (c < NN) g_colcnt[c] = 0;
        }
        // fa: 4,000,000 floats = 1,000,000 float4; 3000 blocks -> 334 float4/block
        const size_t total4 = (size_t)NN * NN / 4;
        size_t per = (total4 + 2999) / 3000;          // 334
        size_t lo = (size_t)bx * per;
        size_t hi = lo + per; if (hi > total4) hi = total4;
        float4 z = make_float4(0.f, 0.f, 0.f, 0.f);
        for (size_t p = lo + tid; p < hi; p += 256) ((float4*)fa)[p] = z;
    }

    if (bx % 3 == 0) {
        // ================= scores + top-20 =================
        int sidb = bx / 3;
        float* s   = sm;                // [TILE][NN] raw scores
        float* e1s = sm + TILE * NN;    // [TILE][NDm]

        int h  = sidb / (NN / TILE);
        int n0 = (sidb % (NN / TILE)) * TILE;

        for (int i = tid; i < TILE * NDm; i += blockDim.x)
            e1s[i] = e1[((size_t)h * NN + n0 + i / NDm) * NDm + (i % NDm)];
        __syncthreads();

        // register-blocked GEMM: each thread -> all 8 rows x 4 consecutive m.
        const float* e2h = e2 + (size_t)h * NDm * NN;
        for (int m0 = tid * 4; m0 < NN; m0 += 1024) {
            float acc[TILE][4];
#pragma unroll
            for (int r = 0; r < TILE; r++)
#pragma unroll
                for (int mm = 0; mm < 4; mm++) acc[r][mm] = 0.f;

#pragma unroll 4
            for (int d4 = 0; d4 < NDm; d4 += 4) {
                float4 e1v[TILE];
#pragma unroll
                for (int r = 0; r < TILE; r++)
                    e1v[r] = *(const float4*)&e1s[r * NDm + d4];
                float4 b0 = *(const float4*)(e2h + (size_t)(d4 + 0) * NN + m0);
                float4 b1 = *(const float4*)(e2h + (size_t)(d4 + 1) * NN + m0);
                float4 b2 = *(const float4*)(e2h + (size_t)(d4 + 2) * NN + m0);
                float4 b3 = *(const float4*)(e2h + (size_t)(d4 + 3) * NN + m0);
#pragma unroll
                for (int r = 0; r < TILE; r++) {
                    acc[r][0] = fmaf(e1v[r].x, b0.x, acc[r][0]);
                    acc[r][1] = fmaf(e1v[r].x, b0.y, acc[r][1]);
                    acc[r][2] = fmaf(e1v[r].x, b0.z, acc[r][2]);
                    acc[r][3] = fmaf(e1v[r].x, b0.w, acc[r][3]);
                    acc[r][0] = fmaf(e1v[r].y, b1.x, acc[r][0]);
                    acc[r][1] = fmaf(e1v[r].y, b1.y, acc[r][1]);
                    acc[r][2] = fmaf(e1v[r].y, b1.z, acc[r][2]);
                    acc[r][3] = fmaf(e1v[r].y, b1.w, acc[r][3]);
                    acc[r][0] = fmaf(e1v[r].z, b2.x, acc[r][0]);
                    acc[r][1] = fmaf(e1v[r].z, b2.y, acc[r][1]);
                    acc[r][2] = fmaf(e1v[r].z, b2.z, acc[r][2]);
                    acc[r][3] = fmaf(e1v[r].z, b2.w, acc[r][3]);
                    acc[r][0] = fmaf(e1v[r].w, b3.x, acc[r][0]);
                    acc[r][1] = fmaf(e1v[r].w, b3.y, acc[r][1]);
                    acc[r][2] = fmaf(e1v[r].w, b3.z, acc[r][2]);
                    acc[r][3] = fmaf(e1v[r].w, b3.w, acc[r][3]);
                }
            }
#pragma unroll
            for (int r = 0; r < TILE; r++)
                *(float4*)&s[r * NN + m0] = *(float4*)acc[r];
        }
        __syncthreads();

        int w = tid >> 5, lane = tid & 31;
        float invT = 1.0f / temp[h];
        float* sw = s + w * NN;

        float v0 = -1.f, v1 = -1.f, v2 = -1.f, v3 = -1.f;
        int   m0i = 0,   m1i = 0,   m2i = 0,   m3i = 0;
#define INSERT_CAND(a, m) do { \
            if ((a) > v3) { \
                if ((a) > v0)      { v3=v2;m3i=m2i; v2=v1;m2i=m1i; v1=v0;m1i=m0i; v0=(a);m0i=(m); } \
                else if ((a) > v1) { v3=v2;m3i=m2i; v2=v1;m2i=m1i; v1=(a);m1i=(m); } \
                else if ((a) > v2) { v3=v2;m3i=m2i; v2=(a);m2i=(m); } \
                else               { v3=(a);m3i=(m); } \
            } } while (0)

        for (int m = lane; m < NN; m += 32) {
            float raw = sw[m];
            float a = (raw < -1e30f) ? -1.f : fmaxf(raw, 0.f) * invT;
            INSERT_CAND(a, m);
        }

        int base = (h * NN + n0 + w) * KK;
        float M = 0.f, ssel = 0.f;
        for (int k = 0; k < KK; k++) {
            float best = v0; int bm = m0i;
#pragma unroll
            for (int o = 16; o; o >>= 1) {
                float ov = __shfl_xor_sync(0xffffffffu, best, o);
                int   oi = __shfl_xor_sync(0xffffffffu, bm,   o);
                if (ov > best || (ov == best && oi < bm)) { best = ov; bm = oi; }
            }
            if (k == 0) M = best;
            float e = __expf(best - M);
            ssel += e;
            if (lane == 0) { g_tki[base + k] = bm; g_tkv[base + k] = e; }
            if (lane == (bm & 31)) {
                sw[bm] = MARKV;
                v0 = v1; m0i = m1i; v1 = v2; m1i = m2i; v2 = v3; m2i = m3i; v3 = -1.f;
                if (v0 < 0.f && k < KK - 1) {
                    v0 = v1 = v2 = v3 = -1.f;
                    for (int m = lane; m < NN; m += 32) {
                        float raw = sw[m];
                        float a = (raw < -1e30f) ? -1.f : fmaxf(raw, 0.f) * invT;
                        INSERT_CAND(a, m);
                    }
                }
            }
        }
#undef INSERT_CAND
        if (lane < KK) g_tkv[base + lane] = g_tkv[base + lane] / ssel;

    } else {
        // ================= support = fp16( xr @ W ), 128 rows/block =================
        int sid = bx - bx / 3 - 1;       // 0..1999
        int row0 = sid * 128;
        float* xs = sm;                  // [128][XS_STRIDE]
        float* wt = sm + 128 * XS_STRIDE; // [64][XS_STRIDE]

        for (int k = tid; k < 1024; k += 256) {
            int d = k >> 4, o4 = (k & 15) * 4;
            float4 w = ((const float4*)W)[k];
            wt[(o4 + 0) * XS_STRIDE + d] = w.x;
            wt[(o4 + 1) * XS_STRIDE + d] = w.y;
            wt[(o4 + 2) * XS_STRIDE + d] = w.z;
            wt[(o4 + 3) * XS_STRIDE + d] = w.w;
        }
        for (int k = tid; k < 2048; k += 256) {
            int rr = k >> 4, f4 = k & 15;
            int r = row0 + rr;
            int bl = r / NN, n = r - bl * NN;
            int b = bl >> 5, l = bl & 31;
            float4 v = ((const float4*)(x + (((size_t)(b * NN + n) * 32) + l) * 64))[f4];
            *(float4*)&xs[rr * XS_STRIDE + f4 * 4] = v;
        }
        __syncthreads();

        int tr = tid & 15, to = tid >> 4;   // 16 row-groups x 16 col-groups
        float acc[8][4];
#pragma unroll
        for (int i = 0; i < 8; i++)
#pragma unroll
            for (int j = 0; j < 4; j++) acc[i][j] = 0.f;

#pragma unroll 4
        for (int d4 = 0; d4 < 64; d4 += 4) {
            float4 xv[8], wv[4];
#pragma unroll
            for (int i = 0; i < 8; i++) xv[i] = *(const float4*)&xs[(tr + 16 * i) * XS_STRIDE + d4];
#pragma unroll
            for (int j = 0; j < 4; j++) wv[j] = *(const float4*)&wt[(to * 4 + j) * XS_STRIDE + d4];
#pragma unroll
            for (int i = 0; i < 8; i++)
#pragma unroll
                for (int j = 0; j < 4; j++) {
                    acc[i][j] = fmaf(xv[i].x, wv[j].x, acc[i][j]);
                    acc[i][j] = fmaf(xv[i].y, wv[j].y, acc[i][j]);
                    acc[i][j] = fmaf(xv[i].z, wv[j].z, acc[i][j]);
                    acc[i][j] = fmaf(xv[i].w, wv[j].w, acc[i][j]);
                }
        }

#pragma unroll
        for (int i = 0; i < 8; i++) {
            int r = row0 + tr + 16 * i;
            __half2 h0 = __floats2half2_rn(acc[i][0], acc[i][1]);
            __half2 h1 = __floats2half2_rn(acc[i][2], acc[i][3]);
            uint2 pk;
            pk.x = *(uint32_t*)&h0;
            pk.y = *(uint32_t*)&h1;
            *(uint2*)(g_supph + (size_t)r * 64 + to * 4) = pk;
        }
    }
}

// ---------------- 2: per-row union + edge MLP -> sparse rows + dense fa ----------------
__global__ __launch_bounds__(256) void build_rows_kernel(
    const float* __restrict__ ew1, const float* __restrict__ eb1,
    const float* __restrict__ ew2, const float* __restrict__ eb2,
    float* __restrict__ fa)
{
    __shared__ float s_ew1[HH * 8];
    __shared__ float s_eb1[8];
    __shared__ float s_ew2[8];
    __shared__ int   s_js[8][80];
    __shared__ float s_vs[8][80];

    int tid = threadIdx.x;
    if (tid < 32) s_ew1[tid] = ew1[tid];
    else if (tid < 40) s_eb1[tid - 32] = eb1[tid - 32];
    else if (tid < 48) s_ew2[tid - 40] = ew2[tid - 40];
    float beta2 = eb2[0];
    __syncthreads();

    int w = tid >> 5, lane = tid & 31;
    int i = blockIdx.x * 8 + w;

    for (int e = lane; e < 80; e += 32) {
        int hh = e / KK, k = e % KK;
        s_js[w][e] = g_tki[(hh * NN + i) * KK + k];
        s_vs[w][e] = g_tkv[(hh * NN + i) * KK + k];
    }
    __syncwarp();

    int cnt = 0;
    for (int p = 0; p < 3; p++) {
        int e = lane + p * 32;
        bool owned = false;
        int j = -1;
        if (e < 80) {
            j = s_js[w][e];
            owned = true;
            for (int q = 0; q < e; q++)
                if (s_js[w][q] == j) { owned = false; break; }
        }
        unsigned bal = __ballot_sync(0xffffffffu, owned);
        int pos = cnt + __popc(bal & ((1u << lane) - 1u));
        if (owned) {
            float v[HH];
            float vsum = 0.f;
#pragma unroll
            for (int hh = 0; hh < HH; hh++) {
                float vv = 0.f;
                for (int k = 0; k < KK; k++)
                    if (s_js[w][hh * KK + k] == j) { vv = s_vs[w][hh * KK + k]; break; }
                v[hh] = vv; vsum += vv;
            }
            float ewv = beta2;
#pragma unroll
            for (int c = 0; c < 8; c++) {
                float hid = s_eb1[c];
#pragma unroll
                for (int hh = 0; hh < HH; hh++) hid = fmaf(v[hh], s_ew1[hh * 8 + c], hid);
                hid = fmaxf(hid, 0.f);
                ewv = fmaf(hid, s_ew2[c], ewv);
            }
            float sig  = 1.f / (1.f + __expf(-ewv));
            float favv = sig * (vsum * 0.25f);
            g_rowj[i * 80 + pos] = j;
            g_rowv[i * 80 + pos] = favv;
            atomicAdd(&g_colcnt[j], 1);
            fa[(size_t)i * NN + j] = favv;
        }
        cnt += __popc(bal);
    }
    if (lane == 0) g_rowcnt[i] = cnt;
}

// ---------------- 3: exclusive scan over column counts (single block) ----------------
__global__ __launch_bounds__(1024) void scan_kernel() {
    __shared__ int buf[1024];
    int t = threadIdx.x;
    int c0 = (2 * t     < NN) ? g_colcnt[2 * t]     : 0;
    int c1 = (2 * t + 1 < NN) ? g_colcnt[2 * t + 1] : 0;
    int psum = c0 + c1;
    buf[t] = psum;
    __syncthreads();
    for (int off = 1; off < 1024; off <<= 1) {
        int tmp = (t >= off) ? buf[t - off] : 0;
        __syncthreads();
        buf[t] += tmp;
        __syncthreads();
    }
    int base = buf[t] - psum;   // exclusive
    if (2 * t < NN)     { g_colptr[2 * t]     = base;      g_colcur[2 * t]     = base; }
    if (2 * t + 1 < NN) { g_colptr[2 * t + 1] = base + c0; g_colcur[2 * t + 1] = base + c0; }
}

// ---------------- 4: fill transposed (per-column) entry lists ----------------
__global__ void fill_kernel() {
    int i = blockIdx.x;
    int t = threadIdx.x;
    int cnt = g_rowcnt[i];
    if (t < cnt) {
        int j = g_rowj[i * 80 + t];
        int pos = atomicAdd(&g_colcur[j], 1);
        g_ci[pos] = i;
        g_cv[pos] = g_rowv[i * 80 + t];
    }
}

// ---------------- 5: sparse out[b,c,l,:] = sum_e w_e * support[bl, j_e, :] + bias ----------------
__global__ __launch_bounds__(256) void spmm_kernel(
    const float* __restrict__ bias, float* __restrict__ out)
{
    __shared__ int   sj[512];
    __shared__ float sv[512];
    int c = blockIdx.x;
    int tid = threadIdx.x;
    int q = tid & 7;        // d octet: d = 8q .. 8q+7
    int g = tid >> 3;       // 0..31
    int start = g_colptr[c], cnt = g_colcnt[c];

    float acc[4][8];
#pragma unroll
    for (int it = 0; it < 4; it++)
#pragma unroll
        for (int j = 0; j < 8; j++) acc[it][j] = 0.f;

    const uint4* supp4 = (const uint4*)g_supph;   // 8 halves per uint4

    for (int off = 0; off < cnt; off += 512) {
        int chunk = min(512, cnt - off);
        for (int e = tid; e < chunk; e += 256) {
            sj[e] = g_ci[start + off + e];
            sv[e] = g_cv[start + off + e];
        }
        __syncthreads();
        for (int e = 0; e < chunk; e++) {
            float wv = sv[e];
            int   i  = sj[e];
#pragma unroll
            for (int it = 0; it < 4; it++) {
                int bl = it * 32 + g;
                uint4 h4 = supp4[(size_t)(bl * NN + i) * 8 + q];
                const __half2* hh = (const __half2*)&h4;
#pragma unroll
                for (int j = 0; j < 4; j++) {
                    float2 f = __half22float2(hh[j]);
                    acc[it][2 * j]     = fmaf(wv, f.x, acc[it][2 * j]);
                    acc[it][2 * j + 1] = fmaf(wv, f.y, acc[it][2 * j + 1]);
                }
            }
        }
        __syncthreads();
    }

    float bv[8];
#pragma unroll
    for (int j = 0; j < 8; j++) bv[j] = bias[q * 8 + j];

#pragma unroll
    for (int it = 0; it < 4; it++) {
        int bl = it * 32 + g;
        int b = bl >> 5, l = bl & 31;
        float4 r0, r1;
        r0.x = acc[it][0] + bv[0]; r0.y = acc[it][1] + bv[1];
        r0.z = acc[it][2] + bv[2]; r0.w = acc[it][3] + bv[3];
        r1.x = acc[it][4] + bv[4]; r1.y = acc[it][5] + bv[5];
        r1.z = acc[it][6] + bv[6]; r1.w = acc[it][7] + bv[7];
        size_t ob = (size_t)((b * NN + c) * 32 + l) * 16 + q * 2;
        ((float4*)out)[ob]     = r0;
        ((float4*)out)[ob + 1] = r1;
    }
}

// ---------------- launch ----------------
extern "C" void kernel_launch(void* const* d_in, const int* in_sizes, int n_in,
                              void* d_out, int out_size)
{
    const float* x      = (const float*)d_in[0];
    const float* e1     = (const float*)d_in[1];
    const float* e2     = (const float*)d_in[2];
    const float* temp   = (const float*)d_in[3];
    const float* ew1    = (const float*)d_in[4];
    const float* eb1    = (const float*)d_in[5];
    const float* ew2    = (const float*)d_in[6];
    const float* eb2    = (const float*)d_in[7];
    const float* weight = (const float*)d_in[8];
    const float* bias   = (const float*)d_in[9];
    float* out = (float*)d_out;

    // final_adj destination: appended after out if there is room, else fallback scratch
    float* fa;
    if (out_size >= OUT_ELEMS + NN * NN) {
        fa = out + OUT_ELEMS;
    } else {
        void* p = nullptr;
        cudaGetSymbolAddress(&p, g_fa_fb);
        fa = (float*)p;
    }

    const int smem_fused = (TILE * NN + TILE * NDm) * sizeof(float);  // 66048 B
    cudaFuncSetAttribute(fused_scores_support_kernel,
                         cudaFuncAttributeMaxDynamicSharedMemorySize, smem_fused);

    fused_scores_support_kernel<<<3000, 256, smem_fused>>>(e1, e2, temp, x, weight, fa);
    build_rows_kernel<<<NN / 8, 256>>>(ew1, eb1, ew2, eb2, fa);
    scan_kernel<<<1, 1024>>>();
    fill_kernel<<<NN, 96>>>();
    spmm_kernel<<<NN, 256>>>(bias, out);
}

// round 15
// speedup vs baseline: 1.2931x; 1.0370x over previous
#include <cuda_runtime.h>
#include <cuda_fp16.h>
#include <cstdint>

#define NN   2000
#define HH   4
#define NDm  64
#define KK   20
#define TILE 8
#define BLT  128          // B*L = 4*32
#define DD   64
#define OUT_ELEMS (4*2000*32*64)
#define NNZ_CAP   (NN*80)
#define MARKV (-3.0e38f)
#define XS_STRIDE 68

// ---------------- scratch (device globals; no allocation) ----------------
__device__ __align__(16) __half g_supph[(size_t)BLT*NN*DD];   // 32.8 MB fp16 support
__device__ int   g_tki[HH*NN*KK];
__device__ float g_tkv[HH*NN*KK];
__device__ int   g_rowj[NN*80];
__device__ float g_rowv[NN*80];
__device__ int   g_rowcnt[NN];
__device__ int   g_colcnt[NN];
__device__ int   g_colptr[NN];
__device__ int   g_colcur[NN];
__device__ int   g_ci[NNZ_CAP];
__device__ float g_cv[NNZ_CAP];
__device__ float g_fa_fb[(size_t)NN*NN];         // fallback final_adj (16 MB)

// ---------------- 1: FUSED scores+topk / support kernel (+ fa/colcnt zeroing) ----------------
// grid = 3000 blocks of 256 threads, 66048 B dyn smem.
//   bx % 3 == 0  -> scores/topk block, id = bx/3           (1000 blocks)
//   else         -> support block,    id = bx - bx/3 - 1   (2000 blocks)
__global__ __launch_bounds__(256) void fused_scores_support_kernel(
    const float* __restrict__ e1, const float* __restrict__ e2,
    const float* __restrict__ temp,
    const float* __restrict__ x, const float* __restrict__ W,
    float* __restrict__ fa)
{
    extern __shared__ float sm[];
    int bx = blockIdx.x;
    int tid = threadIdx.x;

    // ---- zero prologue (disjoint slices; no races) ----
    {
        if (bx < 8) {
            int c = bx * 256 + tid;
            if (c < NN) g_colcnt[c] = 0;
        }
        const size_t total4 = (size_t)NN * NN / 4;
        size_t per = (total4 + 2999) / 3000;
        size_t lo = (size_t)bx * per;
        size_t hi = lo + per; if (hi > total4) hi = total4;
        float4 z = make_float4(0.f, 0.f, 0.f, 0.f);
        for (size_t p = lo + tid; p < hi; p += 256) ((float4*)fa)[p] = z;
    }

    if (bx % 3 == 0) {
        // ================= scores + top-20 =================
        int sidb = bx / 3;
        float* s   = sm;                // [TILE][NN] raw scores
        float* e1s = sm + TILE * NN;    // [TILE][NDm]

        int h  = sidb / (NN / TILE);
        int n0 = (sidb % (NN / TILE)) * TILE;

        for (int i = tid; i < TILE * NDm; i += blockDim.x)
            e1s[i] = e1[((size_t)h * NN + n0 + i / NDm) * NDm + (i % NDm)];
        __syncthreads();

        const float* e2h = e2 + (size_t)h * NDm * NN;
        for (int m0 = tid * 4; m0 < NN; m0 += 1024) {
            float acc[TILE][4];
#pragma unroll
            for (int r = 0; r < TILE; r++)
#pragma unroll
                for (int mm = 0; mm < 4; mm++) acc[r][mm] = 0.f;

#pragma unroll 4
            for (int d4 = 0; d4 < NDm; d4 += 4) {
                float4 e1v[TILE];
#pragma unroll
                for (int r = 0; r < TILE; r++)
                    e1v[r] = *(const float4*)&e1s[r * NDm + d4];
                float4 b0 = *(const float4*)(e2h + (size_t)(d4 + 0) * NN + m0);
                float4 b1 = *(const float4*)(e2h + (size_t)(d4 + 1) * NN + m0);
                float4 b2 = *(const float4*)(e2h + (size_t)(d4 + 2) * NN + m0);
                float4 b3 = *(const float4*)(e2h + (size_t)(d4 + 3) * NN + m0);
#pragma unroll
                for (int r = 0; r < TILE; r++) {
                    acc[r][0] = fmaf(e1v[r].x, b0.x, acc[r][0]);
                    acc[r][1] = fmaf(e1v[r].x, b0.y, acc[r][1]);
                    acc[r][2] = fmaf(e1v[r].x, b0.z, acc[r][2]);
                    acc[r][3] = fmaf(e1v[r].x, b0.w, acc[r][3]);
                    acc[r][0] = fmaf(e1v[r].y, b1.x, acc[r][0]);
                    acc[r][1] = fmaf(e1v[r].y, b1.y, acc[r][1]);
                    acc[r][2] = fmaf(e1v[r].y, b1.z, acc[r][2]);
                    acc[r][3] = fmaf(e1v[r].y, b1.w, acc[r][3]);
                    acc[r][0] = fmaf(e1v[r].z, b2.x, acc[r][0]);
                    acc[r][1] = fmaf(e1v[r].z, b2.y, acc[r][1]);
                    acc[r][2] = fmaf(e1v[r].z, b2.z, acc[r][2]);
                    acc[r][3] = fmaf(e1v[r].z, b2.w, acc[r][3]);
                    acc[r][0] = fmaf(e1v[r].w, b3.x, acc[r][0]);
                    acc[r][1] = fmaf(e1v[r].w, b3.y, acc[r][1]);
                    acc[r][2] = fmaf(e1v[r].w, b3.z, acc[r][2]);
                    acc[r][3] = fmaf(e1v[r].w, b3.w, acc[r][3]);
                }
            }
#pragma unroll
            for (int r = 0; r < TILE; r++)
                *(float4*)&s[r * NN + m0] = *(float4*)acc[r];
        }
        __syncthreads();

        int w = tid >> 5, lane = tid & 31;
        float invT = 1.0f / temp[h];
        float* sw = s + w * NN;

        float v0 = -1.f, v1 = -1.f, v2 = -1.f, v3 = -1.f;
        int   m0i = 0,   m1i = 0,   m2i = 0,   m3i = 0;
#define INSERT_CAND(a, m) do { \
            if ((a) > v3) { \
                if ((a) > v0)      { v3=v2;m3i=m2i; v2=v1;m2i=m1i; v1=v0;m1i=m0i; v0=(a);m0i=(m); } \
                else if ((a) > v1) { v3=v2;m3i=m2i; v2=v1;m2i=m1i; v1=(a);m1i=(m); } \
                else if ((a) > v2) { v3=v2;m3i=m2i; v2=(a);m2i=(m); } \
                else               { v3=(a);m3i=(m); } \
            } } while (0)

        for (int m = lane; m < NN; m += 32) {
            float raw = sw[m];
            float a = (raw < -1e30f) ? -1.f : fmaxf(raw, 0.f) * invT;
            INSERT_CAND(a, m);
        }

        int base = (h * NN + n0 + w) * KK;
        float M = 0.f, ssel = 0.f;
        for (int k = 0; k < KK; k++) {
            float best = v0; int bm = m0i;
#pragma unroll
            for (int o = 16; o; o >>= 1) {
                float ov = __shfl_xor_sync(0xffffffffu, best, o);
                int   oi = __shfl_xor_sync(0xffffffffu, bm,   o);
                if (ov > best || (ov == best && oi < bm)) { best = ov; bm = oi; }
            }
            if (k == 0) M = best;
            float e = __expf(best - M);
            ssel += e;
            if (lane == 0) { g_tki[base + k] = bm; g_tkv[base + k] = e; }
            if (lane == (bm & 31)) {
                sw[bm] = MARKV;
                v0 = v1; m0i = m1i; v1 = v2; m1i = m2i; v2 = v3; m2i = m3i; v3 = -1.f;
                if (v0 < 0.f && k < KK - 1) {
                    v0 = v1 = v2 = v3 = -1.f;
                    for (int m = lane; m < NN; m += 32) {
                        float raw = sw[m];
                        float a = (raw < -1e30f) ? -1.f : fmaxf(raw, 0.f) * invT;
                        INSERT_CAND(a, m);
                    }
                }
            }
        }
#undef INSERT_CAND
        if (lane < KK) g_tkv[base + lane] = g_tkv[base + lane] / ssel;

    } else {
        // ================= support = fp16( xr @ W ), 128 rows/block =================
        int sid = bx - bx / 3 - 1;       // 0..1999
        int row0 = sid * 128;
        float* xs = sm;                  // [128][XS_STRIDE]
        float* wt = sm + 128 * XS_STRIDE; // [64][XS_STRIDE]

        for (int k = tid; k < 1024; k += 256) {
            int d = k >> 4, o4 = (k & 15) * 4;
            float4 w = ((const float4*)W)[k];
            wt[(o4 + 0) * XS_STRIDE + d] = w.x;
            wt[(o4 + 1) * XS_STRIDE + d] = w.y;
            wt[(o4 + 2) * XS_STRIDE + d] = w.z;
            wt[(o4 + 3) * XS_STRIDE + d] = w.w;
        }
        for (int k = tid; k < 2048; k += 256) {
            int rr = k >> 4, f4 = k & 15;
            int r = row0 + rr;
            int bl = r / NN, n = r - bl * NN;
            int b = bl >> 5, l = bl & 31;
            float4 v = ((const float4*)(x + (((size_t)(b * NN + n) * 32) + l) * 64))[f4];
            *(float4*)&xs[rr * XS_STRIDE + f4 * 4] = v;
        }
        __syncthreads();

        int tr = tid & 15, to = tid >> 4;
        float acc[8][4];
#pragma unroll
        for (int i = 0; i < 8; i++)
#pragma unroll
            for (int j = 0; j < 4; j++) acc[i][j] = 0.f;

#pragma unroll 4
        for (int d4 = 0; d4 < 64; d4 += 4) {
            float4 xv[8], wv[4];
#pragma unroll
            for (int i = 0; i < 8; i++) xv[i] = *(const float4*)&xs[(tr + 16 * i) * XS_STRIDE + d4];
#pragma unroll
            for (int j = 0; j < 4; j++) wv[j] = *(const float4*)&wt[(to * 4 + j) * XS_STRIDE + d4];
#pragma unroll
            for (int i = 0; i < 8; i++)
#pragma unroll
                for (int j = 0; j < 4; j++) {
                    acc[i][j] = fmaf(xv[i].x, wv[j].x, acc[i][j]);
                    acc[i][j] = fmaf(xv[i].y, wv[j].y, acc[i][j]);
                    acc[i][j] = fmaf(xv[i].z, wv[j].z, acc[i][j]);
                    acc[i][j] = fmaf(xv[i].w, wv[j].w, acc[i][j]);
                }
        }

#pragma unroll
        for (int i = 0; i < 8; i++) {
            int r = row0 + tr + 16 * i;
            __half2 h0 = __floats2half2_rn(acc[i][0], acc[i][1]);
            __half2 h1 = __floats2half2_rn(acc[i][2], acc[i][3]);
            uint2 pk;
            pk.x = *(uint32_t*)&h0;
            pk.y = *(uint32_t*)&h1;
            *(uint2*)(g_supph + (size_t)r * 64 + to * 4) = pk;
        }
    }
}

// ---------------- 2: per-row union + edge MLP -> sparse rows + dense fa ----------------
__global__ __launch_bounds__(256) void build_rows_kernel(
    const float* __restrict__ ew1, const float* __restrict__ eb1,
    const float* __restrict__ ew2, const float* __restrict__ eb2,
    float* __restrict__ fa)
{
    __shared__ float s_ew1[HH * 8];
    __shared__ float s_eb1[8];
    __shared__ float s_ew2[8];
    __shared__ int   s_js[8][80];
    __shared__ float s_vs[8][80];

    int tid = threadIdx.x;
    if (tid < 32) s_ew1[tid] = ew1[tid];
    else if (tid < 40) s_eb1[tid - 32] = eb1[tid - 32];
    else if (tid < 48) s_ew2[tid - 40] = ew2[tid - 40];
    float beta2 = eb2[0];
    __syncthreads();

    int w = tid >> 5, lane = tid & 31;
    int i = blockIdx.x * 8 + w;

    for (int e = lane; e < 80; e += 32) {
        int hh = e / KK, k = e % KK;
        s_js[w][e] = g_tki[(hh * NN + i) * KK + k];
        s_vs[w][e] = g_tkv[(hh * NN + i) * KK + k];
    }
    __syncwarp();

    int cnt = 0;
    for (int p = 0; p < 3; p++) {
        int e = lane + p * 32;
        bool owned = false;
        int j = -1;
        if (e < 80) {
            j = s_js[w][e];
            owned = true;
            for (int q = 0; q < e; q++)
                if (s_js[w][q] == j) { owned = false; break; }
        }
        unsigned bal = __ballot_sync(0xffffffffu, owned);
        int pos = cnt + __popc(bal & ((1u << lane) - 1u));
        if (owned) {
            float v[HH];
            float vsum = 0.f;
#pragma unroll
            for (int hh = 0; hh < HH; hh++) {
                float vv = 0.f;
                for (int k = 0; k < KK; k++)
                    if (s_js[w][hh * KK + k] == j) { vv = s_vs[w][hh * KK + k]; break; }
                v[hh] = vv; vsum += vv;
            }
            float ewv = beta2;
#pragma unroll
            for (int c = 0; c < 8; c++) {
                float hid = s_eb1[c];
#pragma unroll
                for (int hh = 0; hh < HH; hh++) hid = fmaf(v[hh], s_ew1[hh * 8 + c], hid);
                hid = fmaxf(hid, 0.f);
                ewv = fmaf(hid, s_ew2[c], ewv);
            }
            float sig  = 1.f / (1.f + __expf(-ewv));
            float favv = sig * (vsum * 0.25f);
            g_rowj[i * 80 + pos] = j;
            g_rowv[i * 80 + pos] = favv;
            atomicAdd(&g_colcnt[j], 1);
            fa[(size_t)i * NN + j] = favv;
        }
        cnt += __popc(bal);
    }
    if (lane == 0) g_rowcnt[i] = cnt;
}

// ---------------- 3: exclusive scan over column counts (single block) ----------------
__global__ __launch_bounds__(1024) void scan_kernel() {
    __shared__ int buf[1024];
    int t = threadIdx.x;
    int c0 = (2 * t     < NN) ? g_colcnt[2 * t]     : 0;
    int c1 = (2 * t + 1 < NN) ? g_colcnt[2 * t + 1] : 0;
    int psum = c0 + c1;
    buf[t] = psum;
    __syncthreads();
    for (int off = 1; off < 1024; off <<= 1) {
        int tmp = (t >= off) ? buf[t - off] : 0;
        __syncthreads();
        buf[t] += tmp;
        __syncthreads();
    }
    int base = buf[t] - psum;   // exclusive
    if (2 * t < NN)     { g_colptr[2 * t]     = base;      g_colcur[2 * t]     = base; }
    if (2 * t + 1 < NN) { g_colptr[2 * t + 1] = base + c0; g_colcur[2 * t + 1] = base + c0; }
}

// ---------------- 4: fill transposed (per-column) entry lists ----------------
__global__ void fill_kernel() {
    int i = blockIdx.x;
    int t = threadIdx.x;
    int cnt = g_rowcnt[i];
    if (t < cnt) {
        int j = g_rowj[i * 80 + t];
        int pos = atomicAdd(&g_colcur[j], 1);
        g_ci[pos] = i;
        g_cv[pos] = g_rowv[i * 80 + t];
    }
}

// ---------------- 5: sparse out = A^T * support + bias, bl-split over grid.y ----------------
// grid = (2000, 2); block 256 = 8 d-octets x 32 bl-groups; 2 bl iters per block.
// Per-output accumulation order identical to the 4-it version (e ascending).
__global__ __launch_bounds__(256) void spmm_kernel(
    const float* __restrict__ bias, float* __restrict__ out)
{
    __shared__ int2 sev[512];           // (j, val-bits) packed entries
    int c = blockIdx.x;
    int half = blockIdx.y;              // 0 -> bl 0..63, 1 -> bl 64..127
    int tid = threadIdx.x;
    int q = tid & 7;                    // d octet: d = 8q .. 8q+7
    int g = tid >> 3;                   // 0..31
    int start = g_colptr[c], cnt = g_colcnt[c];
    int itbase = half * 2;

    float acc[2][8];
#pragma unroll
    for (int it = 0; it < 2; it++)
#pragma unroll
        for (int j = 0; j < 8; j++) acc[it][j] = 0.f;

    // base for this thread's (bl-group, octet): plane it advances by 32*NN rows
    const __half* pg = g_supph + ((size_t)(itbase * 32 + g) * NN) * 64 + q * 8;
    const size_t PLANE4 = (size_t)32 * NN * 8;   // 32*NN rows * 8 uint4/row

    for (int off = 0; off < cnt; off += 512) {
        int chunk = min(512, cnt - off);
        for (int e = tid; e < chunk; e += 256) {
            int2 ev;
            ev.x = g_ci[start + off + e];
            ev.y = __float_as_int(g_cv[start + off + e]);
            sev[e] = ev;
        }
        __syncthreads();
#pragma unroll 2
        for (int e = 0; e < chunk; e++) {
            int2 ev = sev[e];
            float wv = __int_as_float(ev.y);
            const uint4* p = (const uint4*)(pg + (size_t)ev.x * 64);
            uint4 h4a = p[0];
            uint4 h4b = p[PLANE4];
            const __half2* ha = (const __half2*)&h4a;
            const __half2* hb = (const __half2*)&h4b;
#pragma unroll
            for (int j = 0; j < 4; j++) {
                float2 fa2 = __half22float2(ha[j]);
                float2 fb2 = __half22float2(hb[j]);
                acc[0][2 * j]     = fmaf(wv, fa2.x, acc[0][2 * j]);
                acc[0][2 * j + 1] = fmaf(wv, fa2.y, acc[0][2 * j + 1]);
                acc[1][2 * j]     = fmaf(wv, fb2.x, acc[1][2 * j]);
                acc[1][2 * j + 1] = fmaf(wv, fb2.y, acc[1][2 * j + 1]);
            }
        }
        __syncthreads();
    }

    float bv[8];
#pragma unroll
    for (int j = 0; j < 8; j++) bv[j] = bias[q * 8 + j];

#pragma unroll
    for (int it = 0; it < 2; it++) {
        int bl = (itbase + it) * 32 + g;
        int b = bl >> 5, l = bl & 31;
        float4 r0, r1;
        r0.x = acc[it][0] + bv[0]; r0.y = acc[it][1] + bv[1];
        r0.z = acc[it][2] + bv[2]; r0.w = acc[it][3] + bv[3];
        r1.x = acc[it][4] + bv[4]; r1.y = acc[it][5] + bv[5];
        r1.z = acc[it][6] + bv[6]; r1.w = acc[it][7] + bv[7];
        size_t ob = (size_t)((b * NN + c) * 32 + l) * 16 + q * 2;
        ((float4*)out)[ob]     = r0;
        ((float4*)out)[ob + 1] = r1;
    }
}

// ---------------- launch ----------------
extern "C" void kernel_launch(void* const* d_in, const int* in_sizes, int n_in,
                              void* d_out, int out_size)
{
    const float* x      = (const float*)d_in[0];
    const float* e1     = (const float*)d_in[1];
    const float* e2     = (const float*)d_in[2];
    const float* temp   = (const float*)d_in[3];
    const float* ew1    = (const float*)d_in[4];
    const float* eb1    = (const float*)d_in[5];
    const float* ew2    = (const float*)d_in[6];
    const float* eb2    = (const float*)d_in[7];
    const float* weight = (const float*)d_in[8];
    const float* bias   = (const float*)d_in[9];
    float* out = (float*)d_out;

    // final_adj destination: appended after out if there is room, else fallback scratch
    float* fa;
    if (out_size >= OUT_ELEMS + NN * NN) {
        fa = out + OUT_ELEMS;
    } else {
        void* p = nullptr;
        cudaGetSymbolAddress(&p, g_fa_fb);
        fa = (float*)p;
    }

    const int smem_fused = (TILE * NN + TILE * NDm) * sizeof(float);  // 66048 B
    cudaFuncSetAttribute(fused_scores_support_kernel,
                         cudaFuncAttributeMaxDynamicSharedMemorySize, smem_fused);

    fused_scores_support_kernel<<<3000, 256, smem_fused>>>(e1, e2, temp, x, weight, fa);
    build_rows_kernel<<<NN / 8, 256>>>(ew1, eb1, ew2, eb2, fa);
    scan_kernel<<<1, 1024>>>();
    fill_kernel<<<NN, 96>>>();
    spmm_kernel<<<dim3(NN, 2), 256>>>(bias, out);
}

// round 16
// speedup vs baseline: 1.2971x; 1.0031x over previous
#include <cuda_runtime.h>
#include <cuda_fp16.h>
#include <cstdint>

#define NN   2000
#define HH   4
#define NDm  64
#define KK   20
#define TILE 8
#define BLT  128          // B*L = 4*32
#define DD   64
#define OUT_ELEMS (4*2000*32*64)
#define NNZ_CAP   (NN*80)
#define MARKV (-3.0e38f)
#define XS_STRIDE 68

// ---------------- scratch (device globals; no allocation) ----------------
__device__ __align__(16) __half g_supph[(size_t)BLT*NN*DD];   // 32.8 MB fp16 support
__device__ int   g_tki[HH*NN*KK];
__device__ float g_tkv[HH*NN*KK];
__device__ int   g_rowj[NN*80];
__device__ float g_rowv[NN*80];
__device__ int   g_rowcnt[NN];
__device__ int   g_colcnt[NN];
__device__ int   g_colptr[NN];
__device__ int   g_colcur[NN];
__device__ int   g_ci[NNZ_CAP];
__device__ float g_cv[NNZ_CAP];
__device__ float g_fa_fb[(size_t)NN*NN];         // fallback final_adj (16 MB)

// packed f32x2 helpers (FFMA2 path — per-lane IEEE fma.rn, bit-exact)
#define PACK_FF(out, lo, hi) \
    asm("mov.b64 %0, {%1, %2};" : "=l"(out) : "f"(lo), "f"(hi))
#define UNPACK_FF(lo, hi, in) \
    asm("mov.b64 {%0, %1}, %2;" : "=f"(lo), "=f"(hi) : "l"(in))
#define FFMA2(acc, a, b) \
    asm("fma.rn.f32x2 %0, %1, %2, %0;" : "+l"(acc) : "l"(a), "l"(b))

// ---------------- 1: FUSED scores+topk / support kernel (+ fa/colcnt zeroing) ----------------
// grid = 3000 blocks of 256 threads, 66048 B dyn smem.
//   bx % 3 == 0  -> scores/topk block, id = bx/3           (1000 blocks)
//   else         -> support block,    id = bx - bx/3 - 1   (2000 blocks)
__global__ __launch_bounds__(256) void fused_scores_support_kernel(
    const float* __restrict__ e1, const float* __restrict__ e2,
    const float* __restrict__ temp,
    const float* __restrict__ x, const float* __restrict__ W,
    float* __restrict__ fa)
{
    extern __shared__ float sm[];
    int bx = blockIdx.x;
    int tid = threadIdx.x;

    // ---- zero prologue (disjoint slices; no races) ----
    {
        if (bx < 8) {
            int c = bx * 256 + tid;
            if (c < NN) g_colcnt[c] = 0;
        }
        const size_t total4 = (size_t)NN * NN / 4;
        size_t per = (total4 + 2999) / 3000;
        size_t lo = (size_t)bx * per;
        size_t hi = lo + per; if (hi > total4) hi = total4;
        float4 z = make_float4(0.f, 0.f, 0.f, 0.f);
        for (size_t p = lo + tid; p < hi; p += 256) ((float4*)fa)[p] = z;
    }

    if (bx % 3 == 0) {
        // ================= scores + top-20 =================
        int sidb = bx / 3;
        float* s   = sm;                // [TILE][NN] raw scores
        float* e1s = sm + TILE * NN;    // [TILE][NDm]

        int h  = sidb / (NN / TILE);
        int n0 = (sidb % (NN / TILE)) * TILE;

        for (int i = tid; i < TILE * NDm; i += blockDim.x)
            e1s[i] = e1[((size_t)h * NN + n0 + i / NDm) * NDm + (i % NDm)];
        __syncthreads();

        const float* e2h = e2 + (size_t)h * NDm * NN;
        for (int m0 = tid * 4; m0 < NN; m0 += 1024) {
            float acc[TILE][4];
#pragma unroll
            for (int r = 0; r < TILE; r++)
#pragma unroll
                for (int mm = 0; mm < 4; mm++) acc[r][mm] = 0.f;

#pragma unroll 4
            for (int d4 = 0; d4 < NDm; d4 += 4) {
                float4 e1v[TILE];
#pragma unroll
                for (int r = 0; r < TILE; r++)
                    e1v[r] = *(const float4*)&e1s[r * NDm + d4];
                float4 b0 = *(const float4*)(e2h + (size_t)(d4 + 0) * NN + m0);
                float4 b1 = *(const float4*)(e2h + (size_t)(d4 + 1) * NN + m0);
                float4 b2 = *(const float4*)(e2h + (size_t)(d4 + 2) * NN + m0);
                float4 b3 = *(const float4*)(e2h + (size_t)(d4 + 3) * NN + m0);
#pragma unroll
                for (int r = 0; r < TILE; r++) {
                    acc[r][0] = fmaf(e1v[r].x, b0.x, acc[r][0]);
                    acc[r][1] = fmaf(e1v[r].x, b0.y, acc[r][1]);
                    acc[r][2] = fmaf(e1v[r].x, b0.z, acc[r][2]);
                    acc[r][3] = fmaf(e1v[r].x, b0.w, acc[r][3]);
                    acc[r][0] = fmaf(e1v[r].y, b1.x, acc[r][0]);
                    acc[r][1] = fmaf(e1v[r].y, b1.y, acc[r][1]);
                    acc[r][2] = fmaf(e1v[r].y, b1.z, acc[r][2]);
                    acc[r][3] = fmaf(e1v[r].y, b1.w, acc[r][3]);
                    acc[r][0] = fmaf(e1v[r].z, b2.x, acc[r][0]);
                    acc[r][1] = fmaf(e1v[r].z, b2.y, acc[r][1]);
                    acc[r][2] = fmaf(e1v[r].z, b2.z, acc[r][2]);
                    acc[r][3] = fmaf(e1v[r].z, b2.w, acc[r][3]);
                    acc[r][0] = fmaf(e1v[r].w, b3.x, acc[r][0]);
                    acc[r][1] = fmaf(e1v[r].w, b3.y, acc[r][1]);
                    acc[r][2] = fmaf(e1v[r].w, b3.z, acc[r][2]);
                    acc[r][3] = fmaf(e1v[r].w, b3.w, acc[r][3]);
                }
            }
#pragma unroll
            for (int r = 0; r < TILE; r++)
                *(float4*)&s[r * NN + m0] = *(float4*)acc[r];
        }
        __syncthreads();

        int w = tid >> 5, lane = tid & 31;
        float invT = 1.0f / temp[h];
        float* sw = s + w * NN;

        float v0 = -1.f, v1 = -1.f, v2 = -1.f, v3 = -1.f;
        int   m0i = 0,   m1i = 0,   m2i = 0,   m3i = 0;
#define INSERT_CAND(a, m) do { \
            if ((a) > v3) { \
                if ((a) > v0)      { v3=v2;m3i=m2i; v2=v1;m2i=m1i; v1=v0;m1i=m0i; v0=(a);m0i=(m); } \
                else if ((a) > v1) { v3=v2;m3i=m2i; v2=v1;m2i=m1i; v1=(a);m1i=(m); } \
                else if ((a) > v2) { v3=v2;m3i=m2i; v2=(a);m2i=(m); } \
                else               { v3=(a);m3i=(m); } \
            } } while (0)

        for (int m = lane; m < NN; m += 32) {
            float raw = sw[m];
            float a = (raw < -1e30f) ? -1.f : fmaxf(raw, 0.f) * invT;
            INSERT_CAND(a, m);
        }

        int base = (h * NN + n0 + w) * KK;
        float M = 0.f, ssel = 0.f;
        for (int k = 0; k < KK; k++) {
            float best = v0; int bm = m0i;
#pragma unroll
            for (int o = 16; o; o >>= 1) {
                float ov = __shfl_xor_sync(0xffffffffu, best, o);
                int   oi = __shfl_xor_sync(0xffffffffu, bm,   o);
                if (ov > best || (ov == best && oi < bm)) { best = ov; bm = oi; }
            }
            if (k == 0) M = best;
            float e = __expf(best - M);
            ssel += e;
            if (lane == 0) { g_tki[base + k] = bm; g_tkv[base + k] = e; }
            if (lane == (bm & 31)) {
                sw[bm] = MARKV;
                v0 = v1; m0i = m1i; v1 = v2; m1i = m2i; v2 = v3; m2i = m3i; v3 = -1.f;
                if (v0 < 0.f && k < KK - 1) {
                    v0 = v1 = v2 = v3 = -1.f;
                    for (int m = lane; m < NN; m += 32) {
                        float raw = sw[m];
                        float a = (raw < -1e30f) ? -1.f : fmaxf(raw, 0.f) * invT;
                        INSERT_CAND(a, m);
                    }
                }
            }
        }
#undef INSERT_CAND
        if (lane < KK) g_tkv[base + lane] = g_tkv[base + lane] / ssel;

    } else {
        // ================= support = fp16( xr @ W ), 128 rows/block =================
        int sid = bx - bx / 3 - 1;       // 0..1999
        int row0 = sid * 128;
        float* xs = sm;                  // [128][XS_STRIDE]
        float* wt = sm + 128 * XS_STRIDE; // [64][XS_STRIDE]

        for (int k = tid; k < 1024; k += 256) {
            int d = k >> 4, o4 = (k & 15) * 4;
            float4 w = ((const float4*)W)[k];
            wt[(o4 + 0) * XS_STRIDE + d] = w.x;
            wt[(o4 + 1) * XS_STRIDE + d] = w.y;
            wt[(o4 + 2) * XS_STRIDE + d] = w.z;
            wt[(o4 + 3) * XS_STRIDE + d] = w.w;
        }
        for (int k = tid; k < 2048; k += 256) {
            int rr = k >> 4, f4 = k & 15;
            int r = row0 + rr;
            int bl = r / NN, n = r - bl * NN;
            int b = bl >> 5, l = bl & 31;
            float4 v = ((const float4*)(x + (((size_t)(b * NN + n) * 32) + l) * 64))[f4];
            *(float4*)&xs[rr * XS_STRIDE + f4 * 4] = v;
        }
        __syncthreads();

        int tr = tid & 15, to = tid >> 4;
        float acc[8][4];
#pragma unroll
        for (int i = 0; i < 8; i++)
#pragma unroll
            for (int j = 0; j < 4; j++) acc[i][j] = 0.f;

#pragma unroll 4
        for (int d4 = 0; d4 < 64; d4 += 4) {
            float4 xv[8], wv[4];
#pragma unroll
            for (int i = 0; i < 8; i++) xv[i] = *(const float4*)&xs[(tr + 16 * i) * XS_STRIDE + d4];
#pragma unroll
            for (int j = 0; j < 4; j++) wv[j] = *(const float4*)&wt[(to * 4 + j) * XS_STRIDE + d4];
#pragma unroll
            for (int i = 0; i < 8; i++)
#pragma unroll
                for (int j = 0; j < 4; j++) {
                    acc[i][j] = fmaf(xv[i].x, wv[j].x, acc[i][j]);
                    acc[i][j] = fmaf(xv[i].y, wv[j].y, acc[i][j]);
                    acc[i][j] = fmaf(xv[i].z, wv[j].z, acc[i][j]);
                    acc[i][j] = fmaf(xv[i].w, wv[j].w, acc[i][j]);
                }
        }

#pragma unroll
        for (int i = 0; i < 8; i++) {
            int r = row0 + tr + 16 * i;
            __half2 h0 = __floats2half2_rn(acc[i][0], acc[i][1]);
            __half2 h1 = __floats2half2_rn(acc[i][2], acc[i][3]);
            uint2 pk;
            pk.x = *(uint32_t*)&h0;
            pk.y = *(uint32_t*)&h1;
            *(uint2*)(g_supph + (size_t)r * 64 + to * 4) = pk;
        }
    }
}

// ---------------- 2: per-row union + edge MLP -> sparse rows + dense fa ----------------
__global__ __launch_bounds__(256) void build_rows_kernel(
    const float* __restrict__ ew1, const float* __restrict__ eb1,
    const float* __restrict__ ew2, const float* __restrict__ eb2,
    float* __restrict__ fa)
{
    __shared__ float s_ew1[HH * 8];
    __shared__ float s_eb1[8];
    __shared__ float s_ew2[8];
    __shared__ int   s_js[8][80];
    __shared__ float s_vs[8][80];

    int tid = threadIdx.x;
    if (tid < 32) s_ew1[tid] = ew1[tid];
    else if (tid < 40) s_eb1[tid - 32] = eb1[tid - 32];
    else if (tid < 48) s_ew2[tid - 40] = ew2[tid - 40];
    float beta2 = eb2[0];
    __syncthreads();

    int w = tid >> 5, lane = tid & 31;
    int i = blockIdx.x * 8 + w;

    for (int e = lane; e < 80; e += 32) {
        int hh = e / KK, k = e % KK;
        s_js[w][e] = g_tki[(hh * NN + i) * KK + k];
        s_vs[w][e] = g_tkv[(hh * NN + i) * KK + k];
    }
    __syncwarp();

    int cnt = 0;
    for (int p = 0; p < 3; p++) {
        int e = lane + p * 32;
        bool owned = false;
        int j = -1;
        if (e < 80) {
            j = s_js[w][e];
            owned = true;
            for (int q = 0; q < e; q++)
                if (s_js[w][q] == j) { owned = false; break; }
        }
        unsigned bal = __ballot_sync(0xffffffffu, owned);
        int pos = cnt + __popc(bal & ((1u << lane) - 1u));
        if (owned) {
            float v[HH];
            float vsum = 0.f;
#pragma unroll
            for (int hh = 0; hh < HH; hh++) {
                float vv = 0.f;
                for (int k = 0; k < KK; k++)
                    if (s_js[w][hh * KK + k] == j) { vv = s_vs[w][hh * KK + k]; break; }
                v[hh] = vv; vsum += vv;
            }
            float ewv = beta2;
#pragma unroll
            for (int c = 0; c < 8; c++) {
                float hid = s_eb1[c];
#pragma unroll
                for (int hh = 0; hh < HH; hh++) hid = fmaf(v[hh], s_ew1[hh * 8 + c], hid);
                hid = fmaxf(hid, 0.f);
                ewv = fmaf(hid, s_ew2[c], ewv);
            }
            float sig  = 1.f / (1.f + __expf(-ewv));
            float favv = sig * (vsum * 0.25f);
            g_rowj[i * 80 + pos] = j;
            g_rowv[i * 80 + pos] = favv;
            atomicAdd(&g_colcnt[j], 1);
            fa[(size_t)i * NN + j] = favv;
        }
        cnt += __popc(bal);
    }
    if (lane == 0) g_rowcnt[i] = cnt;
}

// ---------------- 3: exclusive scan over column counts (single block) ----------------
__global__ __launch_bounds__(1024) void scan_kernel() {
    __shared__ int buf[1024];
    int t = threadIdx.x;
    int c0 = (2 * t     < NN) ? g_colcnt[2 * t]     : 0;
    int c1 = (2 * t + 1 < NN) ? g_colcnt[2 * t + 1] : 0;
    int psum = c0 + c1;
    buf[t] = psum;
    __syncthreads();
    for (int off = 1; off < 1024; off <<= 1) {
        int tmp = (t >= off) ? buf[t - off] : 0;
        __syncthreads();
        buf[t] += tmp;
        __syncthreads();
    }
    int base = buf[t] - psum;   // exclusive
    if (2 * t < NN)     { g_colptr[2 * t]     = base;      g_colcur[2 * t]     = base; }
    if (2 * t + 1 < NN) { g_colptr[2 * t + 1] = base + c0; g_colcur[2 * t + 1] = base + c0; }
}

// ---------------- 4: fill transposed (per-column) entry lists ----------------
__global__ void fill_kernel() {
    int i = blockIdx.x;
    int t = threadIdx.x;
    int cnt = g_rowcnt[i];
    if (t < cnt) {
        int j = g_rowj[i * 80 + t];
        int pos = atomicAdd(&g_colcur[j], 1);
        g_ci[pos] = i;
        g_cv[pos] = g_rowv[i * 80 + t];
    }
}

// ---------------- 5: sparse out = A^T * support + bias, bl-split over grid.y ----------------
// grid = (2000, 2); block 256 = 8 d-octets x 32 bl-groups; 2 bl iters per block.
// Inner loop uses packed fma.rn.f32x2 (FFMA2): per-lane IEEE fma.rn, identical
// per-output accumulation order -> bit-exact vs scalar version.
__global__ __launch_bounds__(256) void spmm_kernel(
    const float* __restrict__ bias, float* __restrict__ out)
{
    __shared__ int2 sev[512];           // (j, val-bits) packed entries
    int c = blockIdx.x;
    int half = blockIdx.y;              // 0 -> bl 0..63, 1 -> bl 64..127
    int tid = threadIdx.x;
    int q = tid & 7;                    // d octet: d = 8q .. 8q+7
    int g = tid >> 3;                   // 0..31
    int start = g_colptr[c], cnt = g_colcnt[c];
    int itbase = half * 2;

    unsigned long long acc2[2][4];
#pragma unroll
    for (int it = 0; it < 2; it++)
#pragma unroll
        for (int j = 0; j < 4; j++) {
            float zz = 0.f;
            PACK_FF(acc2[it][j], zz, zz);
        }

    const __half* pg = g_supph + ((size_t)(itbase * 32 + g) * NN) * 64 + q * 8;
    const size_t PLANE4 = (size_t)32 * NN * 8;   // 32*NN rows * 8 uint4/row

    for (int off = 0; off < cnt; off += 512) {
        int chunk = min(512, cnt - off);
        for (int e = tid; e < chunk; e += 256) {
            int2 ev;
            ev.x = g_ci[start + off + e];
            ev.y = __float_as_int(g_cv[start + off + e]);
            sev[e] = ev;
        }
        __syncthreads();
#pragma unroll 2
        for (int e = 0; e < chunk; e++) {
            int2 ev = sev[e];
            float wv = __int_as_float(ev.y);
            unsigned long long wv2;
            PACK_FF(wv2, wv, wv);
            const uint4* p = (const uint4*)(pg + (size_t)ev.x * 64);
            uint4 h4a = p[0];
            uint4 h4b = p[PLANE4];
            const __half2* ha = (const __half2*)&h4a;
            const __half2* hb = (const __half2*)&h4b;
#pragma unroll
            for (int j = 0; j < 4; j++) {
                float2 fa2 = __half22float2(ha[j]);
                float2 fb2 = __half22float2(hb[j]);
                unsigned long long pa, pb;
                PACK_FF(pa, fa2.x, fa2.y);
                PACK_FF(pb, fb2.x, fb2.y);
                FFMA2(acc2[0][j], wv2, pa);
                FFMA2(acc2[1][j], wv2, pb);
            }
        }
        __syncthreads();
    }

    float bv[8];
#pragma unroll
    for (int j = 0; j < 8; j++) bv[j] = bias[q * 8 + j];

#pragma unroll
    for (int it = 0; it < 2; it++) {
        int bl = (itbase + it) * 32 + g;
        int b = bl >> 5, l = bl & 31;
        float a0, a1, a2, a3, a4, a5, a6, a7;
        UNPACK_FF(a0, a1, acc2[it][0]);
        UNPACK_FF(a2, a3, acc2[it][1]);
        UNPACK_FF(a4, a5, acc2[it][2]);
        UNPACK_FF(a6, a7, acc2[it][3]);
        float4 r0, r1;
        r0.x = a0 + bv[0]; r0.y = a1 + bv[1];
        r0.z = a2 + bv[2]; r0.w = a3 + bv[3];
        r1.x = a4 + bv[4]; r1.y = a5 + bv[5];
        r1.z = a6 + bv[6]; r1.w = a7 + bv[7];
        size_t ob = (size_t)((b * NN + c) * 32 + l) * 16 + q * 2;
        ((float4*)out)[ob]     = r0;
        ((float4*)out)[ob + 1] = r1;
    }
}

// ---------------- launch ----------------
extern "C" void kernel_launch(void* const* d_in, const int* in_sizes, int n_in,
                              void* d_out, int out_size)
{
    const float* x      = (const float*)d_in[0];
    const float* e1     = (const float*)d_in[1];
    const float* e2     = (const float*)d_in[2];
    const float* temp   = (const float*)d_in[3];
    const float* ew1    = (const float*)d_in[4];
    const float* eb1    = (const float*)d_in[5];
    const float* ew2    = (const float*)d_in[6];
    const float* eb2    = (const float*)d_in[7];
    const float* weight = (const float*)d_in[8];
    const float* bias   = (const float*)d_in[9];
    float* out = (float*)d_out;

    // final_adj destination: appended after out if there is room, else fallback scratch
    float* fa;
    if (out_size >= OUT_ELEMS + NN * NN) {
        fa = out + OUT_ELEMS;
    } else {
        void* p = nullptr;
        cudaGetSymbolAddress(&p, g_fa_fb);
        fa = (float*)p;
    }

    const int smem_fused = (TILE * NN + TILE * NDm) * sizeof(float);  // 66048 B
    cudaFuncSetAttribute(fused_scores_support_kernel,
                         cudaFuncAttributeMaxDynamicSharedMemorySize, smem_fused);

    fused_scores_support_kernel<<<3000, 256, smem_fused>>>(e1, e2, temp, x, weight, fa);
    build_rows_kernel<<<NN / 8, 256>>>(ew1, eb1, ew2, eb2, fa);
    scan_kernel<<<1, 1024>>>();
    fill_kernel<<<NN, 96>>>();
    spmm_kernel<<<dim3(NN, 2), 256>>>(bias, out);
}

// round 17
// speedup vs baseline: 1.3014x; 1.0033x over previous
#include <cuda_runtime.h>
#include <cuda_fp16.h>
#include <cstdint>

#define NN   2000
#define HH   4
#define NDm  64
#define KK   20
#define TILE 8
#define BLT  128          // B*L = 4*32
#define DD   64
#define OUT_ELEMS (4*2000*32*64)
#define NNZ_CAP   (NN*80)
#define MARKV (-3.0e38f)
#define XS_STRIDE 68
#define BSF_BLOCKS 250

// ---------------- scratch (device globals; no allocation) ----------------
__device__ __align__(16) __half g_supph[(size_t)BLT*NN*DD];   // 32.8 MB fp16 support
__device__ int   g_tki[HH*NN*KK];
__device__ float g_tkv[HH*NN*KK];
__device__ int   g_rowj[NN*80];
__device__ float g_rowv[NN*80];
__device__ int   g_rowcnt[NN];
__device__ int   g_colcnt[NN];
__device__ int   g_colptr[NN];
__device__ int   g_colcur[NN];
__device__ int   g_done;
__device__ int   g_ci[NNZ_CAP];
__device__ float g_cv[NNZ_CAP];
__device__ float g_fa_fb[(size_t)NN*NN];         // fallback final_adj (16 MB)

// packed f32x2 helpers (FFMA2 path — per-lane IEEE fma.rn, bit-exact)
#define PACK_FF(out, lo, hi) \
    asm("mov.b64 %0, {%1, %2};" : "=l"(out) : "f"(lo), "f"(hi))
#define UNPACK_FF(lo, hi, in) \
    asm("mov.b64 {%0, %1}, %2;" : "=f"(lo), "=f"(hi) : "l"(in))
#define FFMA2(acc, a, b) \
    asm("fma.rn.f32x2 %0, %1, %2, %0;" : "+l"(acc) : "l"(a), "l"(b))

// ---------------- 1: FUSED scores+topk / support kernel (+ zero prologue) ----------------
// grid = 3000 blocks of 256 threads, 66048 B dyn smem.
//   bx % 3 == 0  -> scores/topk block, id = bx/3           (1000 blocks)
//   else         -> support block,    id = bx - bx/3 - 1   (2000 blocks)
__global__ __launch_bounds__(256) void fused_scores_support_kernel(
    const float* __restrict__ e1, const float* __restrict__ e2,
    const float* __restrict__ temp,
    const float* __restrict__ x, const float* __restrict__ W,
    float* __restrict__ fa)
{
    extern __shared__ float sm[];
    int bx = blockIdx.x;
    int tid = threadIdx.x;

    // ---- zero prologue (disjoint slices; no races) ----
    {
        if (bx < 8) {
            int c = bx * 256 + tid;
            if (c < NN) { g_colcnt[c] = 0; g_colcur[c] = 0; }
        }
        if (bx == 8 && tid == 0) g_done = 0;
        const size_t total4 = (size_t)NN * NN / 4;
        size_t per = (total4 + 2999) / 3000;
        size_t lo = (size_t)bx * per;
        size_t hi = lo + per; if (hi > total4) hi = total4;
        float4 z = make_float4(0.f, 0.f, 0.f, 0.f);
        for (size_t p = lo + tid; p < hi; p += 256) ((float4*)fa)[p] = z;
    }

    if (bx % 3 == 0) {
        // ================= scores + top-20 =================
        int sidb = bx / 3;
        float* s   = sm;                // [TILE][NN] raw scores
        float* e1s = sm + TILE * NN;    // [TILE][NDm]

        int h  = sidb / (NN / TILE);
        int n0 = (sidb % (NN / TILE)) * TILE;

        for (int i = tid; i < TILE * NDm; i += blockDim.x)
            e1s[i] = e1[((size_t)h * NN + n0 + i / NDm) * NDm + (i % NDm)];
        __syncthreads();

        const float* e2h = e2 + (size_t)h * NDm * NN;
        for (int m0 = tid * 4; m0 < NN; m0 += 1024) {
            float acc[TILE][4];
#pragma unroll
            for (int r = 0; r < TILE; r++)
#pragma unroll
                for (int mm = 0; mm < 4; mm++) acc[r][mm] = 0.f;

#pragma unroll 4
            for (int d4 = 0; d4 < NDm; d4 += 4) {
                float4 e1v[TILE];
#pragma unroll
                for (int r = 0; r < TILE; r++)
                    e1v[r] = *(const float4*)&e1s[r * NDm + d4];
                float4 b0 = *(const float4*)(e2h + (size_t)(d4 + 0) * NN + m0);
                float4 b1 = *(const float4*)(e2h + (size_t)(d4 + 1) * NN + m0);
                float4 b2 = *(const float4*)(e2h + (size_t)(d4 + 2) * NN + m0);
                float4 b3 = *(const float4*)(e2h + (size_t)(d4 + 3) * NN + m0);
#pragma unroll
                for (int r = 0; r < TILE; r++) {
                    acc[r][0] = fmaf(e1v[r].x, b0.x, acc[r][0]);
                    acc[r][1] = fmaf(e1v[r].x, b0.y, acc[r][1]);
                    acc[r][2] = fmaf(e1v[r].x, b0.z, acc[r][2]);
                    acc[r][3] = fmaf(e1v[r].x, b0.w, acc[r][3]);
                    acc[r][0] = fmaf(e1v[r].y, b1.x, acc[r][0]);
                    acc[r][1] = fmaf(e1v[r].y, b1.y, acc[r][1]);
                    acc[r][2] = fmaf(e1v[r].y, b1.z, acc[r][2]);
                    acc[r][3] = fmaf(e1v[r].y, b1.w, acc[r][3]);
                    acc[r][0] = fmaf(e1v[r].z, b2.x, acc[r][0]);
                    acc[r][1] = fmaf(e1v[r].z, b2.y, acc[r][1]);
                    acc[r][2] = fmaf(e1v[r].z, b2.z, acc[r][2]);
                    acc[r][3] = fmaf(e1v[r].z, b2.w, acc[r][3]);
                    acc[r][0] = fmaf(e1v[r].w, b3.x, acc[r][0]);
                    acc[r][1] = fmaf(e1v[r].w, b3.y, acc[r][1]);
                    acc[r][2] = fmaf(e1v[r].w, b3.z, acc[r][2]);
                    acc[r][3] = fmaf(e1v[r].w, b3.w, acc[r][3]);
                }
            }
#pragma unroll
            for (int r = 0; r < TILE; r++)
                *(float4*)&s[r * NN + m0] = *(float4*)acc[r];
        }
        __syncthreads();

        int w = tid >> 5, lane = tid & 31;
        float invT = 1.0f / temp[h];
        float* sw = s + w * NN;

        float v0 = -1.f, v1 = -1.f, v2 = -1.f, v3 = -1.f;
        int   m0i = 0,   m1i = 0,   m2i = 0,   m3i = 0;
#define INSERT_CAND(a, m) do { \
            if ((a) > v3) { \
                if ((a) > v0)      { v3=v2;m3i=m2i; v2=v1;m2i=m1i; v1=v0;m1i=m0i; v0=(a);m0i=(m); } \
                else if ((a) > v1) { v3=v2;m3i=m2i; v2=v1;m2i=m1i; v1=(a);m1i=(m); } \
                else if ((a) > v2) { v3=v2;m3i=m2i; v2=(a);m2i=(m); } \
                else               { v3=(a);m3i=(m); } \
            } } while (0)

        for (int m = lane; m < NN; m += 32) {
            float raw = sw[m];
            float a = (raw < -1e30f) ? -1.f : fmaxf(raw, 0.f) * invT;
            INSERT_CAND(a, m);
        }

        int base = (h * NN + n0 + w) * KK;
        float M = 0.f, ssel = 0.f;
        for (int k = 0; k < KK; k++) {
            float best = v0; int bm = m0i;
#pragma unroll
            for (int o = 16; o; o >>= 1) {
                float ov = __shfl_xor_sync(0xffffffffu, best, o);
                int   oi = __shfl_xor_sync(0xffffffffu, bm,   o);
                if (ov > best || (ov == best && oi < bm)) { best = ov; bm = oi; }
            }
            if (k == 0) M = best;
            float e = __expf(best - M);
            ssel += e;
            if (lane == 0) { g_tki[base + k] = bm; g_tkv[base + k] = e; }
            if (lane == (bm & 31)) {
                sw[bm] = MARKV;
                v0 = v1; m0i = m1i; v1 = v2; m1i = m2i; v2 = v3; m2i = m3i; v3 = -1.f;
                if (v0 < 0.f && k < KK - 1) {
                    v0 = v1 = v2 = v3 = -1.f;
                    for (int m = lane; m < NN; m += 32) {
                        float raw = sw[m];
                        float a = (raw < -1e30f) ? -1.f : fmaxf(raw, 0.f) * invT;
                        INSERT_CAND(a, m);
                    }
                }
            }
        }
#undef INSERT_CAND
        if (lane < KK) g_tkv[base + lane] = g_tkv[base + lane] / ssel;

    } else {
        // ================= support = fp16( xr @ W ), 128 rows/block =================
        int sid = bx - bx / 3 - 1;       // 0..1999
        int row0 = sid * 128;
        float* xs = sm;                  // [128][XS_STRIDE]
        float* wt = sm + 128 * XS_STRIDE; // [64][XS_STRIDE]

        for (int k = tid; k < 1024; k += 256) {
            int d = k >> 4, o4 = (k & 15) * 4;
            float4 w = ((const float4*)W)[k];
            wt[(o4 + 0) * XS_STRIDE + d] = w.x;
            wt[(o4 + 1) * XS_STRIDE + d] = w.y;
            wt[(o4 + 2) * XS_STRIDE + d] = w.z;
            wt[(o4 + 3) * XS_STRIDE + d] = w.w;
        }
        for (int k = tid; k < 2048; k += 256) {
            int rr = k >> 4, f4 = k & 15;
            int r = row0 + rr;
            int bl = r / NN, n = r - bl * NN;
            int b = bl >> 5, l = bl & 31;
            float4 v = ((const float4*)(x + (((size_t)(b * NN + n) * 32) + l) * 64))[f4];
            *(float4*)&xs[rr * XS_STRIDE + f4 * 4] = v;
        }
        __syncthreads();

        int tr = tid & 15, to = tid >> 4;
        float acc[8][4];
#pragma unroll
        for (int i = 0; i < 8; i++)
#pragma unroll
            for (int j = 0; j < 4; j++) acc[i][j] = 0.f;

#pragma unroll 4
        for (int d4 = 0; d4 < 64; d4 += 4) {
            float4 xv[8], wv[4];
#pragma unroll
            for (int i = 0; i < 8; i++) xv[i] = *(const float4*)&xs[(tr + 16 * i) * XS_STRIDE + d4];
#pragma unroll
            for (int j = 0; j < 4; j++) wv[j] = *(const float4*)&wt[(to * 4 + j) * XS_STRIDE + d4];
#pragma unroll
            for (int i = 0; i < 8; i++)
#pragma unroll
                for (int j = 0; j < 4; j++) {
                    acc[i][j] = fmaf(xv[i].x, wv[j].x, acc[i][j]);
                    acc[i][j] = fmaf(xv[i].y, wv[j].y, acc[i][j]);
                    acc[i][j] = fmaf(xv[i].z, wv[j].z, acc[i][j]);
                    acc[i][j] = fmaf(xv[i].w, wv[j].w, acc[i][j]);
                }
        }

#pragma unroll
        for (int i = 0; i < 8; i++) {
            int r = row0 + tr + 16 * i;
            __half2 h0 = __floats2half2_rn(acc[i][0], acc[i][1]);
            __half2 h1 = __floats2half2_rn(acc[i][2], acc[i][3]);
            uint2 pk;
            pk.x = *(uint32_t*)&h0;
            pk.y = *(uint32_t*)&h1;
            *(uint2*)(g_supph + (size_t)r * 64 + to * 4) = pk;
        }
    }
}

// ---------------- 2: build + scan + fill, single kernel with grid arrive/spin ----------------
// grid = 250 blocks x 256 threads — all resident simultaneously (low smem/regs),
// so the spin barrier cannot deadlock. g_done/g_colcur reset in fused prologue.
__global__ __launch_bounds__(256) void build_scan_fill_kernel(
    const float* __restrict__ ew1, const float* __restrict__ eb1,
    const float* __restrict__ ew2, const float* __restrict__ eb2,
    float* __restrict__ fa)
{
    __shared__ float s_ew1[HH * 8];
    __shared__ float s_eb1[8];
    __shared__ float s_ew2[8];
    __shared__ int   s_js[8][80];
    __shared__ float s_vs[8][80];
    __shared__ int   spart[256];
    __shared__ int   sptr[NN];

    int tid = threadIdx.x;
    if (tid < 32) s_ew1[tid] = ew1[tid];
    else if (tid < 40) s_eb1[tid - 32] = eb1[tid - 32];
    else if (tid < 48) s_ew2[tid - 40] = ew2[tid - 40];
    float beta2 = eb2[0];
    __syncthreads();

    int w = tid >> 5, lane = tid & 31;
    int i = blockIdx.x * 8 + w;

    // ---- phase 1: build rows (identical math to R15 build_rows) ----
    for (int e = lane; e < 80; e += 32) {
        int hh = e / KK, k = e % KK;
        s_js[w][e] = g_tki[(hh * NN + i) * KK + k];
        s_vs[w][e] = g_tkv[(hh * NN + i) * KK + k];
    }
    __syncwarp();

    int cnt = 0;
    for (int p = 0; p < 3; p++) {
        int e = lane + p * 32;
        bool owned = false;
        int j = -1;
        if (e < 80) {
            j = s_js[w][e];
            owned = true;
            for (int q = 0; q < e; q++)
                if (s_js[w][q] == j) { owned = false; break; }
        }
        unsigned bal = __ballot_sync(0xffffffffu, owned);
        int pos = cnt + __popc(bal & ((1u << lane) - 1u));
        if (owned) {
            float v[HH];
            float vsum = 0.f;
#pragma unroll
            for (int hh = 0; hh < HH; hh++) {
                float vv = 0.f;
                for (int k = 0; k < KK; k++)
                    if (s_js[w][hh * KK + k] == j) { vv = s_vs[w][hh * KK + k]; break; }
                v[hh] = vv; vsum += vv;
            }
            float ewv = beta2;
#pragma unroll
            for (int c = 0; c < 8; c++) {
                float hid = s_eb1[c];
#pragma unroll
                for (int hh = 0; hh < HH; hh++) hid = fmaf(v[hh], s_ew1[hh * 8 + c], hid);
                hid = fmaxf(hid, 0.f);
                ewv = fmaf(hid, s_ew2[c], ewv);
            }
            float sig  = 1.f / (1.f + __expf(-ewv));
            float favv = sig * (vsum * 0.25f);
            g_rowj[i * 80 + pos] = j;
            g_rowv[i * 80 + pos] = favv;
            atomicAdd(&g_colcnt[j], 1);
            fa[(size_t)i * NN + j] = favv;
        }
        cnt += __popc(bal);
    }
    if (lane == 0) g_rowcnt[i] = cnt;

    // ---- grid barrier: arrive + spin (all 250 blocks resident) ----
    __threadfence();
    __syncthreads();
    if (tid == 0) {
        atomicAdd(&g_done, 1);
        while (atomicAdd(&g_done, 0) < BSF_BLOCKS) { }
    }
    __syncthreads();
    __threadfence();

    // ---- phase 2: redundant per-block exclusive scan of colcnt -> sptr ----
    {
        int base8 = tid * 8;
        int loc[8];
        int ssum = 0;
#pragma unroll
        for (int k = 0; k < 8; k++) {
            int idx = base8 + k;
            int vv = (idx < NN) ? g_colcnt[idx] : 0;
            loc[k] = ssum; ssum += vv;
        }
        spart[tid] = ssum;
        __syncthreads();
        for (int off = 1; off < 256; off <<= 1) {
            int tmp = (tid >= off) ? spart[tid - off] : 0;
            __syncthreads();
            spart[tid] += tmp;
            __syncthreads();
        }
        int bbase = (tid > 0) ? spart[tid - 1] : 0;
#pragma unroll
        for (int k = 0; k < 8; k++) {
            int idx = base8 + k;
            if (idx < NN) sptr[idx] = bbase + loc[k];
        }
        __syncthreads();
        if (blockIdx.x == 0)
            for (int c = tid; c < NN; c += 256) g_colptr[c] = sptr[c];
    }

    // ---- phase 3: fill this block's own rows into column lists ----
    {
        int rc = g_rowcnt[i];          // own block's row (visible)
        for (int t = lane; t < rc; t += 32) {
            int j = g_rowj[i * 80 + t];
            int pos = sptr[j] + atomicAdd(&g_colcur[j], 1);
            g_ci[pos] = i;
            g_cv[pos] = g_rowv[i * 80 + t];
        }
    }
}

// ---------------- 3: sparse out = A^T * support + bias, bl-split over grid.y ----------------
// grid = (2000, 2); block 256 = 8 d-octets x 32 bl-groups; 2 bl iters per block.
__global__ __launch_bounds__(256) void spmm_kernel(
    const float* __restrict__ bias, float* __restrict__ out)
{
    __shared__ int2 sev[512];           // (j, val-bits) packed entries
    int c = blockIdx.x;
    int half = blockIdx.y;              // 0 -> bl 0..63, 1 -> bl 64..127
    int tid = threadIdx.x;
    int q = tid & 7;                    // d octet: d = 8q .. 8q+7
    int g = tid >> 3;                   // 0..31
    int start = g_colptr[c], cnt = g_colcnt[c];
    int itbase = half * 2;

    unsigned long long acc2[2][4];
#pragma unroll
    for (int it = 0; it < 2; it++)
#pragma unroll
        for (int j = 0; j < 4; j++) {
            float zz = 0.f;
            PACK_FF(acc2[it][j], zz, zz);
        }

    const __half* pg = g_supph + ((size_t)(itbase * 32 + g) * NN) * 64 + q * 8;
    const size_t PLANE4 = (size_t)32 * NN * 8;   // 32*NN rows * 8 uint4/row

    for (int off = 0; off < cnt; off += 512) {
        int chunk = min(512, cnt - off);
        for (int e = tid; e < chunk; e += 256) {
            int2 ev;
            ev.x = g_ci[start + off + e];
            ev.y = __float_as_int(g_cv[start + off + e]);
            sev[e] = ev;
        }
        __syncthreads();
#pragma unroll 2
        for (int e = 0; e < chunk; e++) {
            int2 ev = sev[e];
            float wv = __int_as_float(ev.y);
            unsigned long long wv2;
            PACK_FF(wv2, wv, wv);
            const uint4* p = (const uint4*)(pg + (size_t)ev.x * 64);
            uint4 h4a = p[0];
            uint4 h4b = p[PLANE4];
            const __half2* ha = (const __half2*)&h4a;
            const __half2* hb = (const __half2*)&h4b;
#pragma unroll
            for (int j = 0; j < 4; j++) {
                float2 fa2 = __half22float2(ha[j]);
                float2 fb2 = __half22float2(hb[j]);
                unsigned long long pa, pb;
                PACK_FF(pa, fa2.x, fa2.y);
                PACK_FF(pb, fb2.x, fb2.y);
                FFMA2(acc2[0][j], wv2, pa);
                FFMA2(acc2[1][j], wv2, pb);
            }
        }
        __syncthreads();
    }

    float bv[8];
#pragma unroll
    for (int j = 0; j < 8; j++) bv[j] = bias[q * 8 + j];

#pragma unroll
    for (int it = 0; it < 2; it++) {
        int bl = (itbase + it) * 32 + g;
        int b = bl >> 5, l = bl & 31;
        float a0, a1, a2, a3, a4, a5, a6, a7;
        UNPACK_FF(a0, a1, acc2[it][0]);
        UNPACK_FF(a2, a3, acc2[it][1]);
        UNPACK_FF(a4, a5, acc2[it][2]);
        UNPACK_FF(a6, a7, acc2[it][3]);
        float4 r0, r1;
        r0.x = a0 + bv[0]; r0.y = a1 + bv[1];
        r0.z = a2 + bv[2]; r0.w = a3 + bv[3];
        r1.x = a4 + bv[4]; r1.y = a5 + bv[5];
        r1.z = a6 + bv[6]; r1.w = a7 + bv[7];
        size_t ob = (size_t)((b * NN + c) * 32 + l) * 16 + q * 2;
        ((float4*)out)[ob]     = r0;
        ((float4*)out)[ob + 1] = r1;
    }
}

// ---------------- launch ----------------
extern "C" void kernel_launch(void* const* d_in, const int* in_sizes, int n_in,
                              void* d_out, int out_size)
{
    const float* x      = (const float*)d_in[0];
    const float* e1     = (const float*)d_in[1];
    const float* e2     = (const float*)d_in[2];
    const float* temp   = (const float*)d_in[3];
    const float* ew1    = (const float*)d_in[4];
    const float* eb1    = (const float*)d_in[5];
    const float* ew2    = (const float*)d_in[6];
    const float* eb2    = (const float*)d_in[7];
    const float* weight = (const float*)d_in[8];
    const float* bias   = (const float*)d_in[9];
    float* out = (float*)d_out;

    // final_adj destination: appended after out if there is room, else fallback scratch
    float* fa;
    if (out_size >= OUT_ELEMS + NN * NN) {
        fa = out + OUT_ELEMS;
    } else {
        void* p = nullptr;
        cudaGetSymbolAddress(&p, g_fa_fb);
        fa = (float*)p;
    }

    const int smem_fused = (TILE * NN + TILE * NDm) * sizeof(float);  // 66048 B
    cudaFuncSetAttribute(fused_scores_support_kernel,
                         cudaFuncAttributeMaxDynamicSharedMemorySize, smem_fused);

    fused_scores_support_kernel<<<3000, 256, smem_fused>>>(e1, e2, temp, x, weight, fa);
    build_scan_fill_kernel<<<BSF_BLOCKS, 256>>>(ew1, eb1, ew2, eb2, fa);
    spmm_kernel<<<dim3(NN, 2), 256>>>(bias, out);
}